// round 16
// baseline (speedup 1.0000x reference)
#include <cuda_runtime.h>

#define NN 8
#define CC 32
#define KK 4
#define DD 24
#define HH 64
#define WW 64
#define HW (HH*WW)        // 4096
#define DHW (DD*HH*WW)    // 98304
#define WPER (CC*CC*27)   // 27648 weights per sample

// -------- device scratch (no runtime allocation allowed) --------
__device__ float g_stats[NN*CC*45];          // 45 boundary stats per (n,c)
__device__ float g_att[NN*KK];               // softmax attention
__device__ float g_weff[NN*WPER];            // per-sample effective 3x3x3 weights

// ============================================================================
// Kernel A: per-(n,c) boundary statistics of x.
// Layout per (n,c), 45 floats:
//  0: T (total sum)
//  1..4:  Pd[d] for d in {0,1,22,23}
//  5..6:  Ph[h] for h in {0,63}
//  7..8:  Pw[w] for w in {0,63}
//  9..16: Edh[di][hj]  (9+di*2+hj)
// 17..24: Edw[di][wj]
// 25..28: Ehw[hj][wj]
// 29..44: corners x[d,h,w] (29 + di*4 + hj*2 + wj)
// ============================================================================
__global__ void stats_kernel(const float* __restrict__ x) {
    const int nc  = blockIdx.x;
    const int tid = threadIdx.x;
    const float* xb = x + nc * DHW;

    float T = 0.f;
    float pd[4]     = {0.f,0.f,0.f,0.f};
    float ph[2]     = {0.f,0.f};
    float pw[2]     = {0.f,0.f};
    float edh[4][2] = {{0.f,0.f},{0.f,0.f},{0.f,0.f},{0.f,0.f}};
    float edw[4][2] = {{0.f,0.f},{0.f,0.f},{0.f,0.f},{0.f,0.f}};
    float ehw[2][2] = {{0.f,0.f},{0.f,0.f}};

    // boundary depth planes d in {0,1,22,23} (unrolled -> static register indices)
    #pragma unroll
    for (int s4 = 0; s4 < 4; s4++) {
        const int dv = (s4 == 0) ? 0 : (s4 == 1) ? 1 : (s4 == 2) ? (DD-2) : (DD-1);
        const float* xp = xb + dv * HW;
        for (int i = tid; i < HW; i += 256) {
            float v = xp[i];
            int h = i >> 6, w = i & 63;
            T += v; pd[s4] += v;
            if (h == 0)    { ph[0] += v; edh[s4][0] += v; if (w == 0) ehw[0][0] += v; if (w == WW-1) ehw[0][1] += v; }
            if (h == HH-1) { ph[1] += v; edh[s4][1] += v; if (w == 0) ehw[1][0] += v; if (w == WW-1) ehw[1][1] += v; }
            if (w == 0)    { pw[0] += v; edw[s4][0] += v; }
            if (w == WW-1) { pw[1] += v; edw[s4][1] += v; }
        }
    }
    // interior depth planes
    for (int d = 2; d < DD-2; d++) {
        const float* xp = xb + d * HW;
        for (int i = tid; i < HW; i += 256) {
            float v = xp[i];
            int h = i >> 6, w = i & 63;
            T += v;
            if (h == 0)    { ph[0] += v; if (w == 0) ehw[0][0] += v; if (w == WW-1) ehw[0][1] += v; }
            if (h == HH-1) { ph[1] += v; if (w == 0) ehw[1][0] += v; if (w == WW-1) ehw[1][1] += v; }
            if (w == 0)    pw[0] += v;
            if (w == WW-1) pw[1] += v;
        }
    }

    float v29[29];
    v29[0] = T;
    #pragma unroll
    for (int i = 0; i < 4; i++) v29[1+i] = pd[i];
    v29[5] = ph[0]; v29[6] = ph[1]; v29[7] = pw[0]; v29[8] = pw[1];
    #pragma unroll
    for (int i = 0; i < 4; i++) {
        v29[ 9+i*2] = edh[i][0]; v29[10+i*2] = edh[i][1];
        v29[17+i*2] = edw[i][0]; v29[18+i*2] = edw[i][1];
    }
    v29[25] = ehw[0][0]; v29[26] = ehw[0][1]; v29[27] = ehw[1][0]; v29[28] = ehw[1][1];

    // deterministic reduction: warp shfl, then fixed-order cross-warp sum
    __shared__ float sred[29][8];
    const int lane = tid & 31, wid = tid >> 5;
    #pragma unroll
    for (int j = 0; j < 29; j++) {
        float t = v29[j];
        #pragma unroll
        for (int o = 16; o > 0; o >>= 1) t += __shfl_down_sync(0xffffffffu, t, o);
        if (lane == 0) sred[j][wid] = t;
    }
    __syncthreads();
    if (tid < 29) {
        float t = 0.f;
        #pragma unroll
        for (int w2 = 0; w2 < 8; w2++) t += sred[tid][w2];
        g_stats[nc*45 + tid] = t;
    }
    // 16 corner values, read directly
    if (tid >= 32 && tid < 48) {
        int t  = tid - 32;
        int di = t >> 2, hj = (t >> 1) & 1, wj = t & 1;
        int dv = (di == 0) ? 0 : (di == 1) ? 1 : (di == 2) ? (DD-2) : (DD-1);
        g_stats[nc*45 + 29 + t] = xb[dv*HW + (hj*(HH-1))*WW + wj*(WW-1)];
    }
}

// ============================================================================
// Kernel B1: attention. Fold attention-conv weights into 45-coef vectors
// (box-sum is linear in the stats), then xa[n,k] = sum_c <wst[k,c], stats[n,c]>,
// softmax over k.
// ============================================================================
__global__ void attn_kernel(const float* __restrict__ aw1, const float* __restrict__ ab1,
                            const float* __restrict__ aw2, const float* __restrict__ ab2,
                            const float* __restrict__ aw3, const float* __restrict__ ab3) {
    __shared__ float swst[KK*CC][45];
    const int tid = threadIdx.x; // 32 threads

    // phase 1: each thread builds 4 (k,c) coefficient vectors
    for (int pi = 0; pi < 4; pi++) {
        int p = tid * 4 + pi;
        int k = p >> 5, c = p & 31;
        float wst[45];
        #pragma unroll
        for (int j = 0; j < 45; j++) wst[j] = 0.f;
        wst[0] = aw1[k*CC + c];   // 1x1x1 pad-0 branch: coefficient on T only

        auto accum = [&](float w, int fd, int bd, int fh, int bh, int fw, int bw) {
            float md[4] = { fd>=1?1.f:0.f, fd>=2?1.f:0.f, bd>=2?1.f:0.f, bd>=1?1.f:0.f };
            float mh[2] = { fh>=1?1.f:0.f, bh>=1?1.f:0.f };
            float mw[2] = { fw>=1?1.f:0.f, bw>=1?1.f:0.f };
            // box = T - SD - SH - SW + SDH + SDW + SHW - SDHW (inclusion-exclusion)
            wst[0] += w;
            #pragma unroll
            for (int i = 0; i < 4; i++) wst[1+i] -= w * md[i];
            wst[5] -= w*mh[0]; wst[6] -= w*mh[1];
            wst[7] -= w*mw[0]; wst[8] -= w*mw[1];
            #pragma unroll
            for (int i = 0; i < 4; i++) {
                #pragma unroll
                for (int j = 0; j < 2; j++) {
                    wst[ 9+i*2+j] += w * md[i] * mh[j];
                    wst[17+i*2+j] += w * md[i] * mw[j];
                }
            }
            #pragma unroll
            for (int j = 0; j < 2; j++) {
                #pragma unroll
                for (int l = 0; l < 2; l++) {
                    wst[25+j*2+l] += w * mh[j] * mw[l];
                    #pragma unroll
                    for (int i = 0; i < 4; i++)
                        wst[29+i*4+j*2+l] -= w * md[i] * mh[j] * mw[l];
                }
            }
        };

        // aw2: 3x3x3 pad (1,1,1):  f = max(0,o-1), b = max(0,1-o)
        for (int od = 0; od < 3; od++)
            for (int oh = 0; oh < 3; oh++)
                for (int ow = 0; ow < 3; ow++)
                    accum(aw2[(k*CC + c)*27 + od*9 + oh*3 + ow],
                          max(0, od-1), max(0, 1-od),
                          max(0, oh-1), max(0, 1-oh),
                          max(0, ow-1), max(0, 1-ow));
        // aw3: 5x3x3 pad (2,1,1):  depth f = max(0,o-2), b = max(0,2-o)
        for (int od = 0; od < 5; od++)
            for (int oh = 0; oh < 3; oh++)
                for (int ow = 0; ow < 3; ow++)
                    accum(aw3[(k*CC + c)*45 + od*9 + oh*3 + ow],
                          max(0, od-2), max(0, 2-od),
                          max(0, oh-1), max(0, 1-oh),
                          max(0, ow-1), max(0, 1-ow));

        #pragma unroll
        for (int j = 0; j < 45; j++) swst[p][j] = wst[j];
    }
    __syncthreads();

    // phase 2: one thread per (n,k)
    const int n = tid >> 2, k = tid & 3;
    float acc = 0.f;
    for (int c = 0; c < CC; c++) {
        const float* sp = g_stats + (n*CC + c)*45;
        const float* wp = swst[k*CC + c];
        #pragma unroll
        for (int j = 0; j < 45; j++) acc = fmaf(sp[j], wp[j], acc);
    }
    float xa = acc * (1.f / (float)DHW) + ab1[k] + ab2[k] + ab3[k];

    // softmax over k (4 consecutive lanes per n)
    float m = xa;
    m = fmaxf(m, __shfl_xor_sync(0xffffffffu, m, 1));
    m = fmaxf(m, __shfl_xor_sync(0xffffffffu, m, 2));
    float e = expf(xa - m);
    float s = e;
    s += __shfl_xor_sync(0xffffffffu, s, 1);
    s += __shfl_xor_sync(0xffffffffu, s, 2);
    g_att[n*KK + k] = e / s;
}

// ============================================================================
// Kernel B2: per-sample effective weights  weff[n] = conv_w + sum_k att[n,k]*weight[k]
// ============================================================================
__global__ void weff_kernel(const float* __restrict__ weight, const float* __restrict__ conv_w) {
    int idx = blockIdx.x * 256 + threadIdx.x;
    if (idx >= NN * WPER) return;
    int n = idx / WPER, j = idx - n * WPER;
    float r = conv_w[j];
    #pragma unroll
    for (int k = 0; k < KK; k++) r = fmaf(g_att[n*KK + k], weight[k*WPER + j], r);
    g_weff[idx] = r;
}

// ============================================================================
// Kernel C: main 3x3x3 conv with per-sample weights + bias.
// Block = (h-tile of 8, d, n): computes 8h x 64w x 32co outputs.
// Thread = (tco in 0..3, th in 0..7, tw in 0..7): 8co x 8w register tile.
// C chunked by 4; x tile in smem (row stride 67 -> conflict-free), weights
// broadcast via LDS.128.
// ============================================================================
__global__ __launch_bounds__(256) void conv_kernel(const float* __restrict__ x,
                                                   const float* __restrict__ conv_b,
                                                   float* __restrict__ out) {
    const int ht = blockIdx.x, d = blockIdx.y, n = blockIdx.z;
    const int h0 = ht * 8;
    const int tid = threadIdx.x;
    const int tco = tid >> 6, th = (tid >> 3) & 7, tw = tid & 7, tw8 = tw * 8;

    __shared__ __align__(16) float xs[4][3][10][67];   // [c][kd][h][w] (w=0 <-> global -1)
    __shared__ __align__(16) float ws[4][27][32];      // [c][koff][co]

    float acc[8][8];
    #pragma unroll
    for (int u = 0; u < 8; u++)
        #pragma unroll
        for (int ow = 0; ow < 8; ow++) acc[u][ow] = 0.f;

    for (int cb = 0; cb < CC; cb += 4) {
        __syncthreads();
        // load x tile (zero-padded borders)
        for (int idx = tid; idx < 4*3*10*67; idx += 256) {
            int c  = idx / 2010;  int r  = idx - c  * 2010;
            int kd = r  / 670;    int r2 = r  - kd * 670;
            int hh = r2 / 67;     int w2 = r2 - hh * 67;
            int gd = d + kd - 1, gh = h0 + hh - 1, gw = w2 - 1;
            float v = 0.f;
            if (w2 < 66 && (unsigned)gd < DD && (unsigned)gh < HH && (unsigned)gw < WW)
                v = x[(((n*CC + cb + c)*DD + gd)*HH + gh)*WW + gw];
            (&xs[0][0][0][0])[idx] = v;
        }
        // load weight tile
        for (int idx = tid; idx < 4*27*32; idx += 256) {
            int c = idx / 864; int rr = idx - c * 864;
            int koff = rr >> 5; int co = rr & 31;
            (&ws[0][0][0])[idx] = g_weff[((n*CC + co)*CC + cb + c)*27 + koff];
        }
        __syncthreads();

        #pragma unroll
        for (int c = 0; c < 4; c++) {
            #pragma unroll
            for (int kd = 0; kd < 3; kd++) {
                #pragma unroll
                for (int kh = 0; kh < 3; kh++) {
                    float xr[10];
                    #pragma unroll
                    for (int j = 0; j < 10; j++) xr[j] = xs[c][kd][th + kh][tw8 + j];
                    float wv[3][8];
                    #pragma unroll
                    for (int kw = 0; kw < 3; kw++) {
                        const float4* wp = (const float4*)&ws[c][kd*9 + kh*3 + kw][tco*8];
                        float4 a = wp[0], b = wp[1];
                        wv[kw][0]=a.x; wv[kw][1]=a.y; wv[kw][2]=a.z; wv[kw][3]=a.w;
                        wv[kw][4]=b.x; wv[kw][5]=b.y; wv[kw][6]=b.z; wv[kw][7]=b.w;
                    }
                    #pragma unroll
                    for (int kw = 0; kw < 3; kw++)
                        #pragma unroll
                        for (int u = 0; u < 8; u++)
                            #pragma unroll
                            for (int ow = 0; ow < 8; ow++)
                                acc[u][ow] = fmaf(wv[kw][u], xr[ow + kw], acc[u][ow]);
                }
            }
        }
    }

    // epilogue: bias + vectorized store
    #pragma unroll
    for (int u = 0; u < 8; u++) {
        int co = tco*8 + u;
        float b = conv_b[co];
        int base = (((n*CC + co)*DD + d)*HH + (h0 + th))*WW + tw8;
        float4 o0 = make_float4(acc[u][0]+b, acc[u][1]+b, acc[u][2]+b, acc[u][3]+b);
        float4 o1 = make_float4(acc[u][4]+b, acc[u][5]+b, acc[u][6]+b, acc[u][7]+b);
        *(float4*)&out[base]     = o0;
        *(float4*)&out[base + 4] = o1;
    }
}

// ============================================================================
extern "C" void kernel_launch(void* const* d_in, const int* in_sizes, int n_in,
                              void* d_out, int out_size) {
    const float* x      = (const float*)d_in[0];
    const float* weight = (const float*)d_in[1];
    const float* conv_w = (const float*)d_in[2];
    const float* conv_b = (const float*)d_in[3];
    const float* aw1    = (const float*)d_in[4];
    const float* ab1    = (const float*)d_in[5];
    const float* aw2    = (const float*)d_in[6];
    const float* ab2    = (const float*)d_in[7];
    const float* aw3    = (const float*)d_in[8];
    const float* ab3    = (const float*)d_in[9];
    float* out = (float*)d_out;

    stats_kernel<<<NN*CC, 256>>>(x);
    attn_kernel<<<1, 32>>>(aw1, ab1, aw2, ab2, aw3, ab3);
    weff_kernel<<<(NN*WPER + 255)/256, 256>>>(weight, conv_w);
    conv_kernel<<<dim3(8, DD, NN), 256>>>(x, conv_b, out);
}